// round 14
// baseline (speedup 1.0000x reference)
#include <cuda_runtime.h>
#include <cuda_fp16.h>
#include <cstdint>
#include <math.h>

// DenseHyperbolic: fused GEMM (mma.sync m16n8k16, plain fp16 with fp32
// accumulate) + analytic hyperbolic epilogue.
//   g = v'(col0=0) @ W ; out_j = Aw*g_j + Ab*bias_j ; out_0 = sqrt(c2)*cosh(.)
//
// R13: L1 62.7% binding, issue 22% -> LSU under-utilized from LDSM->MMA
// dependency heads. R14: hoist all 6 LDSM4 (4 A + 2 B) to the chunk top for
// memory ILP; fully unroll the 16-chunk loop (stage selects/offsets become
// immediates). Same numerics as R13 (plain fp16, rel_err 2.2e-4).
// Warp grid 1Mx8N, warp-private cp.async pipelines, 48KB/CTA, 2 CTAs/SM.

constexpr int D   = 256;
constexpr int BM  = 64;
constexpr int NCH = 16;            // chunks of K=16
constexpr int NT  = 256;
constexpr int A_BYTES = 32768;     // 16 chunks x 2KB (hi only)
constexpr int WSTG_B  = 1024;      // per warp per stage (32-col slice, hi only)
constexpr int SMEM_DYN = A_BYTES + 8 * 2 * WSTG_B;   // 48 KB

#define EPSF       1e-4f
#define ACOSH_MINF 1.0001f
#define CLIPF      8.0f

// W image (hi only): [16 chunks][32 ngroups][2 tiles: hiK0|hiK1][64 halves]
__device__ __half w_img[16 * 4096];

__device__ __forceinline__ uint32_t smem_u32(const void* p) {
    uint32_t a;
    asm("{ .reg .u64 t; cvta.to.shared.u64 t, %1; cvt.u32.u64 %0, t; }"
        : "=r"(a) : "l"(p));
    return a;
}
__device__ __forceinline__ uint32_t packh(__half a, __half b) {
    __half2 h = __halves2half2(a, b);
    return *reinterpret_cast<uint32_t*>(&h);
}

#define MMAF16(C, A, b0, b1) \
    asm volatile("mma.sync.aligned.m16n8k16.row.col.f32.f16.f16.f32 " \
        "{%0,%1,%2,%3}, {%4,%5,%6,%7}, {%8,%9}, {%0,%1,%2,%3};" \
        : "+f"((C)[0]), "+f"((C)[1]), "+f"((C)[2]), "+f"((C)[3]) \
        : "r"((A)[0]), "r"((A)[1]), "r"((A)[2]), "r"((A)[3]), \
          "r"(b0), "r"(b1))

#define LDSM4(R, addr) \
    asm volatile("ldmatrix.sync.aligned.m8n8.x4.shared.b16 {%0,%1,%2,%3}, [%4];" \
        : "=r"((R)[0]), "=r"((R)[1]), "=r"((R)[2]), "=r"((R)[3]) : "r"(addr))

#define CP_ASYNC16(dst_u32, src_ptr) \
    asm volatile("cp.async.cg.shared.global [%0], [%1], 16;" \
                 :: "r"(dst_u32), "l"(src_ptr))
#define CP_COMMIT() asm volatile("cp.async.commit_group;")
#define CP_WAIT0()  asm volatile("cp.async.wait_group 0;" ::: "memory")
#define CP_WAIT1()  asm volatile("cp.async.wait_group 1;" ::: "memory")

// ---- prep: W[k][n] row-major -> fragment-tiled fp16 (hi) image ----
__global__ void prep_w(const float* __restrict__ W) {
    int t = blockIdx.x * 256 + threadIdx.x;      // 8192 tasks
    int c  = t >> 9;                             // k16 chunk
    int rm = t & 511;
    int ng = rm >> 4;                            // n group (8 cols)
    int kt = (rm >> 3) & 1;
    int rr = rm & 7;                             // n within group
    int n  = ng * 8 + rr;
    int kb = c * 16 + kt * 8;
    __half h[8];
    #pragma unroll
    for (int j = 0; j < 8; ++j)
        h[j] = __float2half_rn(W[(size_t)(kb + j) * 256 + n]);
    size_t base = (size_t)c * 4096 + ng * 128 + kt * 64 + rr * 8;   // halves
    *reinterpret_cast<uint4*>(w_img + base) = *reinterpret_cast<const uint4*>(h);
}

// ---- main kernel ----
__global__ __launch_bounds__(NT, 2)
void dh_mma(const float* __restrict__ V,
            const float* __restrict__ cin_p,
            const float* __restrict__ cout_p,
            const float* __restrict__ bias,
            float* __restrict__ out)
{
    extern __shared__ __align__(16) char smc[];   // A 32KB | warp stages 16KB
    const int tid  = threadIdx.x;
    const int lane = tid & 31;
    const int wid  = tid >> 5;
    const int wn   = wid;             // 0..7 (N); warp tile = 64 rows x 32 cols
    const int row0 = blockIdx.x * BM;
    const uint32_t smem0 = smem_u32(smc);

    // epilogue alias region (inside warp-stage area; used only after mainloop)
    float* al     = reinterpret_cast<float*>(smc + A_BYTES);
    float* sbias  = al;               // 256
    float* sgp    = al + 256;         // 64 x 8
    float* sdgp   = al + 768;         // 64 x 8
    float* svsum  = al + 1280;        // 64
    float* sAw    = al + 1344;
    float* sAb    = al + 1408;
    float* sO0    = al + 1472;
    float* sred   = al + 1536;        // 8
    float* sSb    = al + 1544;

    // ---- warp-private W slice cp.async (1KB contiguous: ngroups wn*4..+3) --
    auto cp_w = [&](int i, int stg) {
        const __half* src = w_img + (size_t)i * 4096 + wn * 512;
        uint32_t dst = smem0 + A_BYTES + (uint32_t)(wid * 2 + stg) * WSTG_B;
        #pragma unroll
        for (int j = 0; j < 2; ++j) {
            int f = lane + j * 32;               // 16B units, 0..63
            CP_ASYNC16(dst + f * 16, src + f * 8);
        }
        CP_COMMIT();
    };

    // lead-2 prologue flies during the A conversion
    cp_w(0, 0);
    cp_w(1, 1);

    // ---- A prologue: convert 64x256 tile to hi fp16, resident in smem ----
    const int lr = tid >> 2;
    const int q  = tid & 3;
    const uint32_t aStsOff = (uint32_t)(((lr >> 3) * 2 + (q >> 1)) * 128
                                        + (lr & 7) * 16 + (q & 1) * 8);
    float svloc = 0.f;
    {
        const float* vrow = V + (size_t)(row0 + lr) * D + q * 4;
        #pragma unroll 4
        for (int i = 0; i < NCH; ++i) {
            float4 x = *reinterpret_cast<const float4*>(vrow + i * 16);
            if (i == 0 && q == 0) x.x = 0.f;          // zero time coordinate
            svloc += x.x * x.x + x.y * x.y + x.z * x.z + x.w * x.w;
            __half h0 = __float2half_rn(x.x), h1 = __float2half_rn(x.y);
            __half h2 = __float2half_rn(x.z), h3 = __float2half_rn(x.w);
            char* dst = smc + i * 2048 + aStsOff;
            *reinterpret_cast<uint2*>(dst) =
                make_uint2(packh(h0, h1), packh(h2, h3));
        }
    }

    // ldmatrix lane offsets: A tile = 16 sub-tiles [rowgroup*2 + ktile]
    uint32_t aoff[4];
    {
        int m = lane >> 3;
        int tsel = ((m & 1) << 1) | (m >> 1);    // matrix -> tile {0,2,1,3}
        #pragma unroll
        for (int mt = 0; mt < 4; ++mt)
            aoff[mt] = (uint32_t)((mt * 4 + tsel) * 128 + (lane & 7) * 16);
    }
    const uint32_t boff = (uint32_t)((lane >> 3) * 128 + (lane & 7) * 16);
    const uint32_t wbase = smem0 + A_BYTES + (uint32_t)(wid * 2) * WSTG_B + boff;

    // A tile visible to all warps (the ONLY CTA barrier before the epilogue)
    __syncthreads();

    float acc[4][4][4];
    #pragma unroll
    for (int mt = 0; mt < 4; ++mt)
        #pragma unroll
        for (int nt = 0; nt < 4; ++nt)
            #pragma unroll
            for (int e = 0; e < 4; ++e) acc[mt][nt][e] = 0.f;

    // ---- mainloop: warp-private pipeline, NO CTA barriers, fully unrolled --
    #pragma unroll
    for (int i = 0; i < NCH; ++i) {
        if (i < NCH - 1) { CP_WAIT1(); } else { CP_WAIT0(); }   // chunk i done
        __syncwarp();                          // cross-lane visibility

        // all 6 LDSM up front: maximum memory ILP
        const uint32_t ab = smem0 + i * 2048;
        const uint32_t wb = wbase + (uint32_t)(i & 1) * WSTG_B;
        uint32_t bq[2][4];
        LDSM4(bq[0], wb);
        LDSM4(bq[1], wb + 512);
        uint32_t ah[4][4];
        #pragma unroll
        for (int mt = 0; mt < 4; ++mt) LDSM4(ah[mt], ab + aoff[mt]);

        #pragma unroll
        for (int np = 0; np < 2; ++np) {
            #pragma unroll
            for (int mt = 0; mt < 4; ++mt) {
                MMAF16(acc[mt][np * 2],     ah[mt], bq[np][0], bq[np][1]);
                MMAF16(acc[mt][np * 2 + 1], ah[mt], bq[np][2], bq[np][3]);
            }
        }

        // refill the stage just consumed (lead-2); issue-order after the MMAs
        if (i + 2 < NCH) cp_w(i + 2, i & 1);
    }
    __syncthreads();                   // all warps done; alias region reusable

    // ---- Sv + bias into alias region ----
    svloc += __shfl_xor_sync(~0u, svloc, 1);
    svloc += __shfl_xor_sync(~0u, svloc, 2);
    if (q == 0) svsum[lr] = svloc;
    {
        float bv = (tid == 0) ? 0.f : __ldg(&bias[tid - 1]);
        sbias[tid] = bv;
        float sq = bv * bv;
        #pragma unroll
        for (int o = 16; o > 0; o >>= 1) sq += __shfl_xor_sync(~0u, sq, o);
        if (lane == 0) sred[wid] = sq;
    }
    __syncthreads();
    if (tid == 0) {
        float s = 0.f;
        #pragma unroll
        for (int i = 0; i < 8; i++) s += sred[i];
        *sSb = s;
    }

    // per-thread partial Sg/dg over its 8 columns x 8 rows
    float psg[8], pdg[8];
    #pragma unroll
    for (int e = 0; e < 8; ++e) { psg[e] = 0.f; pdg[e] = 0.f; }
    const bool isc0 = (wn == 0 && (lane & 3) == 0);   // col0 owner when nt==0
    #pragma unroll
    for (int nt = 0; nt < 4; ++nt) {
        float2 bf = *reinterpret_cast<const float2*>(
            &sbias[wn * 32 + nt * 8 + 2 * (lane & 3)]);
        #pragma unroll
        for (int mt = 0; mt < 4; ++mt) {
            const float* C = acc[mt][nt];
            if (!(isc0 && nt == 0)) {             // exclude column 0
                psg[mt * 2]     = fmaf(C[0], C[0], psg[mt * 2]);
                pdg[mt * 2]     = fmaf(C[0], bf.x, pdg[mt * 2]);
                psg[mt * 2 + 1] = fmaf(C[2], C[2], psg[mt * 2 + 1]);
                pdg[mt * 2 + 1] = fmaf(C[2], bf.x, pdg[mt * 2 + 1]);
            }
            psg[mt * 2]     = fmaf(C[1], C[1], psg[mt * 2]);
            pdg[mt * 2]     = fmaf(C[1], bf.y, pdg[mt * 2]);
            psg[mt * 2 + 1] = fmaf(C[3], C[3], psg[mt * 2 + 1]);
            pdg[mt * 2 + 1] = fmaf(C[3], bf.y, pdg[mt * 2 + 1]);
        }
    }
    #pragma unroll
    for (int e = 0; e < 8; ++e) {
        psg[e] += __shfl_xor_sync(~0u, psg[e], 1);
        psg[e] += __shfl_xor_sync(~0u, psg[e], 2);
        pdg[e] += __shfl_xor_sync(~0u, pdg[e], 1);
        pdg[e] += __shfl_xor_sync(~0u, pdg[e], 2);
    }
    if ((lane & 3) == 0) {
        #pragma unroll
        for (int mt = 0; mt < 4; ++mt) {
            #pragma unroll
            for (int rp = 0; rp < 2; ++rp) {
                int r = mt * 16 + rp * 8 + (lane >> 2);
                sgp[r * 8 + wn]  = psg[mt * 2 + rp];
                sdgp[r * 8 + wn] = pdg[mt * 2 + rp];
            }
        }
    }
    __syncthreads();

    if (tid < 64) {
        float Sg = 0.f, dg = 0.f;
        #pragma unroll
        for (int e = 0; e < 8; ++e) { Sg += sgp[tid * 8 + e]; dg += sdgp[tid * 8 + e]; }

        const float c   = *cin_p;
        const float c2  = *cout_p;
        const float sqc = sqrtf(c);
        const float sq2 = sqrtf(c2);
        const float Sb  = *sSb;
        const float Sv  = svsum[tid];

        const float v0p  = sqrtf(c + Sv);
        const float m    = (sqc * acoshf(fmaxf(v0p / sqc - EPSF, ACOSH_MINF)))
                           / (sqrtf(Sv) + EPSF);
        const float Sw   = m * m * Sg;
        const float dw   = m * dg;
        const float n    = sqrtf(Sw) / sqc + EPSF;
        const float ncl  = fminf(n, CLIPF);
        const float ch   = coshf(ncl);
        const float sfac = sinhf(ncl) / n;
        const float T    = sfac * sfac * Sw;
        const float hp0  = sqrtf(c + T);
        const float dd   = sqc * acoshf(fmaxf(ch, ACOSH_MINF));
        const float d2   = sqc * acoshf(fmaxf(hp0 / sqc - EPSF, ACOSH_MINF));
        const float u0   = sqc - hp0 * hp0 / sqc;
        const float suj2 = (hp0 * hp0 / c) * T;
        const float nrmu = sqrtf(suj2 - u0 * u0);
        const float mlt  = d2 / (nrmu + EPSF);
        const float alph = 1.f - mlt * (hp0 / sqc) * sfac;
        const float m2   = dw / (dd * dd);
        const float beta = alph * m2;
        const float bt0  = -(mlt * u0) * m2;
        const float btsq = bt0 * bt0 + Sb - 2.f * beta * dw + beta * beta * Sw;
        const float nb   = sqrtf(btsq) / sqc + EPSF;
        const float nbcl = fminf(nb, CLIPF);
        const float chb  = coshf(nbcl);
        const float sfb  = sinhf(nbcl) / nb;
        const float gam  = chb * sfac - sfb * beta;
        const float del  = sfb;
        const float Sbi  = gam * gam * Sw + 2.f * gam * del * dw + del * del * Sb;
        const float p0   = sqrtf(c + Sbi);
        const float d3   = sqc * acoshf(fmaxf(p0 / sqc - EPSF, ACOSH_MINF));
        const float qn   = sqrtf(Sbi);
        const float mlt3 = d3 / (qn + EPSF);
        const float nf   = mlt3 * qn / sq2 + EPSF;
        const float nfcl = fminf(nf, CLIPF);
        const float phi  = (sinhf(nfcl) / nf) * mlt3;
        sAw[tid] = phi * gam * m;
        sAb[tid] = phi * del;
        sO0[tid] = sq2 * coshf(nfcl);
    }
    __syncthreads();

    // stores: each warp covers cols wn*32..+31 of all 64 rows
    #pragma unroll
    for (int mt = 0; mt < 4; ++mt) {
        #pragma unroll
        for (int rp = 0; rp < 2; ++rp) {
            int r = mt * 16 + rp * 8 + (lane >> 2);
            float Aw = sAw[r], Ab = sAb[r];
            float* orow = out + (size_t)(row0 + r) * D;
            #pragma unroll
            for (int nt = 0; nt < 4; ++nt) {
                float2 bf = *reinterpret_cast<const float2*>(
                    &sbias[wn * 32 + nt * 8 + 2 * (lane & 3)]);
                float g0 = acc[mt][nt][rp * 2];
                float g1 = acc[mt][nt][rp * 2 + 1];
                float2 o;
                o.x = fmaf(Aw, g0, Ab * bf.x);
                o.y = fmaf(Aw, g1, Ab * bf.y);
                if (wn == 0 && nt == 0 && (lane & 3) == 0) o.x = sO0[r];
                *reinterpret_cast<float2*>(
                    orow + wn * 32 + nt * 8 + 2 * (lane & 3)) = o;
            }
        }
    }
}

extern "C" void kernel_launch(void* const* d_in, const int* in_sizes, int n_in,
                              void* d_out, int out_size)
{
    const float* V    = (const float*)d_in[0];
    const float* cin  = (const float*)d_in[1];
    const float* cout = (const float*)d_in[2];
    const float* W    = (const float*)d_in[3];
    const float* bias = (const float*)d_in[4];
    float* out = (float*)d_out;

    const int nrow = in_sizes[0] / D;             // 131072

    cudaFuncSetAttribute(dh_mma, cudaFuncAttributeMaxDynamicSharedMemorySize,
                         SMEM_DYN);

    prep_w<<<32, 256>>>(W);
    dh_mma<<<nrow / BM, NT, SMEM_DYN>>>(V, cin, cout, bias, out);
}

// round 15
// speedup vs baseline: 1.0199x; 1.0199x over previous
#include <cuda_runtime.h>
#include <cuda_fp16.h>
#include <cstdint>
#include <math.h>

// DenseHyperbolic: fused GEMM (mma.sync m16n8k16, plain fp16, fp32 accum)
// + analytic hyperbolic epilogue.
//   g = v'(col0=0) @ W ; out_j = Aw*g_j + Ab*bias_j ; out_0 = sqrt(c2)*cosh(.)
//
// R14: L1 62% binding; B's GMEM->smem->LDSM path is pure overhead for a tiny
// L1/L2-resident W image. R15: prep writes W in EXACT per-lane fragment order
// (what ldmatrix.x4 would produce), so the mainloop loads B fragments with
// 2 LDG.128 per warp per chunk. cp.async/waits/stage-smem/syncwarp all gone;
// per-chunk L1 wavefronts 256 -> 192 per CTA. A stays smem-resident via one
// prologue conversion. 32KB smem/CTA, 2 CTAs/SM. Numerics == R13/R14.

constexpr int D   = 256;
constexpr int BM  = 64;
constexpr int NCH = 16;            // chunks of K=16
constexpr int NT  = 256;
constexpr int A_BYTES = 32768;     // 16 chunks x 2KB (hi only)
constexpr int SMEM_DYN = A_BYTES; // epilogue aliases A region after mainloop

#define EPSF       1e-4f
#define ACOSH_MINF 1.0001f
#define CLIPF      8.0f

// W fragment image, lane-exact: [16 chunks][8 wn][2 np][32 lanes][16B]
// lane l, reg j = tile(ng0+(j>>1), kt=j&1) row (l>>2), k-halves 2(l&3),+1.
__device__ uint4 w_frag[16 * 512];   // 128 KB

__device__ __forceinline__ uint32_t smem_u32(const void* p) {
    uint32_t a;
    asm("{ .reg .u64 t; cvta.to.shared.u64 t, %1; cvt.u32.u64 %0, t; }"
        : "=r"(a) : "l"(p));
    return a;
}
__device__ __forceinline__ uint32_t packh(__half a, __half b) {
    __half2 h = __halves2half2(a, b);
    return *reinterpret_cast<uint32_t*>(&h);
}

#define MMAF16(C, A, b0, b1) \
    asm volatile("mma.sync.aligned.m16n8k16.row.col.f32.f16.f16.f32 " \
        "{%0,%1,%2,%3}, {%4,%5,%6,%7}, {%8,%9}, {%0,%1,%2,%3};" \
        : "+f"((C)[0]), "+f"((C)[1]), "+f"((C)[2]), "+f"((C)[3]) \
        : "r"((A)[0]), "r"((A)[1]), "r"((A)[2]), "r"((A)[3]), \
          "r"(b0), "r"(b1))

#define LDSM4(R, addr) \
    asm volatile("ldmatrix.sync.aligned.m8n8.x4.shared.b16 {%0,%1,%2,%3}, [%4];" \
        : "=r"((R)[0]), "=r"((R)[1]), "=r"((R)[2]), "=r"((R)[3]) : "r"(addr))

// ---- prep: W[k][n] row-major -> lane-exact fp16 fragment image ----
__global__ void prep_w(const float* __restrict__ W) {
    int t = blockIdx.x * 256 + threadIdx.x;      // 8192 tasks (one 16B each)
    int c   = t >> 9;                            // k16 chunk
    int rem = t & 511;
    int wn  = rem >> 6;
    int np  = (rem >> 5) & 1;
    int l   = rem & 31;
    int ng0 = wn * 4 + np * 2;
    uint32_t r[4];
    #pragma unroll
    for (int j = 0; j < 4; ++j) {
        int ng = ng0 + (j >> 1);
        int kt = j & 1;
        int n  = ng * 8 + (l >> 2);
        int k0 = c * 16 + kt * 8 + 2 * (l & 3);
        __half h0 = __float2half_rn(W[(size_t)k0 * 256 + n]);
        __half h1 = __float2half_rn(W[(size_t)(k0 + 1) * 256 + n]);
        r[j] = packh(h0, h1);
    }
    w_frag[t] = make_uint4(r[0], r[1], r[2], r[3]);
}

// ---- main kernel ----
__global__ __launch_bounds__(NT, 2)
void dh_mma(const float* __restrict__ V,
            const float* __restrict__ cin_p,
            const float* __restrict__ cout_p,
            const float* __restrict__ bias,
            float* __restrict__ out)
{
    extern __shared__ __align__(16) char smc[];   // A 32KB (epilogue aliases)
    const int tid  = threadIdx.x;
    const int lane = tid & 31;
    const int wid  = tid >> 5;
    const int wn   = wid;             // 0..7 (N); warp tile = 64 rows x 32 cols
    const int row0 = blockIdx.x * BM;
    const uint32_t smem0 = smem_u32(smc);

    // epilogue alias region (A region; used only after the mainloop barrier)
    float* al     = reinterpret_cast<float*>(smc);
    float* sbias  = al;               // 256
    float* sgp    = al + 256;         // 64 x 8
    float* sdgp   = al + 768;         // 64 x 8
    float* svsum  = al + 1280;        // 64
    float* sAw    = al + 1344;
    float* sAb    = al + 1408;
    float* sO0    = al + 1472;
    float* sred   = al + 1536;        // 8
    float* sSb    = al + 1544;

    // ---- A prologue: convert 64x256 tile to hi fp16, resident in smem ----
    const int lr = tid >> 2;
    const int q  = tid & 3;
    const uint32_t aStsOff = (uint32_t)(((lr >> 3) * 2 + (q >> 1)) * 128
                                        + (lr & 7) * 16 + (q & 1) * 8);
    float svloc = 0.f;
    {
        const float* vrow = V + (size_t)(row0 + lr) * D + q * 4;
        #pragma unroll 4
        for (int i = 0; i < NCH; ++i) {
            float4 x = *reinterpret_cast<const float4*>(vrow + i * 16);
            if (i == 0 && q == 0) x.x = 0.f;          // zero time coordinate
            svloc += x.x * x.x + x.y * x.y + x.z * x.z + x.w * x.w;
            __half h0 = __float2half_rn(x.x), h1 = __float2half_rn(x.y);
            __half h2 = __float2half_rn(x.z), h3 = __float2half_rn(x.w);
            char* dst = smc + i * 2048 + aStsOff;
            *reinterpret_cast<uint2*>(dst) =
                make_uint2(packh(h0, h1), packh(h2, h3));
        }
    }

    // ldmatrix lane offsets: A tile = 16 sub-tiles [rowgroup*2 + ktile]
    uint32_t aoff[4];
    {
        int m = lane >> 3;
        int tsel = ((m & 1) << 1) | (m >> 1);    // matrix -> tile {0,2,1,3}
        #pragma unroll
        for (int mt = 0; mt < 4; ++mt)
            aoff[mt] = (uint32_t)((mt * 4 + tsel) * 128 + (lane & 7) * 16);
    }

    // B fragment base for this warp (uint4 index): [c*512 + wn*64 + np*32 + lane]
    const uint4* wfb = w_frag + wn * 64 + lane;

    // A tile visible to all warps (the ONLY CTA barrier before the epilogue)
    __syncthreads();

    float acc[4][4][4];
    #pragma unroll
    for (int mt = 0; mt < 4; ++mt)
        #pragma unroll
        for (int nt = 0; nt < 4; ++nt)
            #pragma unroll
            for (int e = 0; e < 4; ++e) acc[mt][nt][e] = 0.f;

    // ---- mainloop: LDG B fragments + LDSM A + MMA; no barriers, no waits --
    #pragma unroll
    for (int i = 0; i < NCH; ++i) {
        uint4 b0 = __ldg(wfb + i * 512);
        uint4 b1 = __ldg(wfb + i * 512 + 32);

        const uint32_t ab = smem0 + i * 2048;
        uint32_t ah[4][4];
        #pragma unroll
        for (int mt = 0; mt < 4; ++mt) LDSM4(ah[mt], ab + aoff[mt]);

        #pragma unroll
        for (int mt = 0; mt < 4; ++mt) {
            MMAF16(acc[mt][0], ah[mt], b0.x, b0.y);
            MMAF16(acc[mt][1], ah[mt], b0.z, b0.w);
            MMAF16(acc[mt][2], ah[mt], b1.x, b1.y);
            MMAF16(acc[mt][3], ah[mt], b1.z, b1.w);
        }
    }
    __syncthreads();                   // all warps done; A region reusable

    // ---- Sv + bias into alias region ----
    svloc += __shfl_xor_sync(~0u, svloc, 1);
    svloc += __shfl_xor_sync(~0u, svloc, 2);
    if (q == 0) svsum[lr] = svloc;     // NOTE: svsum aliases A region — but
                                       // writes happen after the barrier ✓
    {
        float bv = (tid == 0) ? 0.f : __ldg(&bias[tid - 1]);
        sbias[tid] = bv;
        float sq = bv * bv;
        #pragma unroll
        for (int o = 16; o > 0; o >>= 1) sq += __shfl_xor_sync(~0u, sq, o);
        if (lane == 0) sred[wid] = sq;
    }
    __syncthreads();
    if (tid == 0) {
        float s = 0.f;
        #pragma unroll
        for (int i = 0; i < 8; i++) s += sred[i];
        *sSb = s;
    }

    // per-thread partial Sg/dg over its 8 columns x 8 rows
    float psg[8], pdg[8];
    #pragma unroll
    for (int e = 0; e < 8; ++e) { psg[e] = 0.f; pdg[e] = 0.f; }
    const bool isc0 = (wn == 0 && (lane & 3) == 0);   // col0 owner when nt==0
    #pragma unroll
    for (int nt = 0; nt < 4; ++nt) {
        float2 bf = *reinterpret_cast<const float2*>(
            &sbias[wn * 32 + nt * 8 + 2 * (lane & 3)]);
        #pragma unroll
        for (int mt = 0; mt < 4; ++mt) {
            const float* C = acc[mt][nt];
            if (!(isc0 && nt == 0)) {             // exclude column 0
                psg[mt * 2]     = fmaf(C[0], C[0], psg[mt * 2]);
                pdg[mt * 2]     = fmaf(C[0], bf.x, pdg[mt * 2]);
                psg[mt * 2 + 1] = fmaf(C[2], C[2], psg[mt * 2 + 1]);
                pdg[mt * 2 + 1] = fmaf(C[2], bf.x, pdg[mt * 2 + 1]);
            }
            psg[mt * 2]     = fmaf(C[1], C[1], psg[mt * 2]);
            pdg[mt * 2]     = fmaf(C[1], bf.y, pdg[mt * 2]);
            psg[mt * 2 + 1] = fmaf(C[3], C[3], psg[mt * 2 + 1]);
            pdg[mt * 2 + 1] = fmaf(C[3], bf.y, pdg[mt * 2 + 1]);
        }
    }
    #pragma unroll
    for (int e = 0; e < 8; ++e) {
        psg[e] += __shfl_xor_sync(~0u, psg[e], 1);
        psg[e] += __shfl_xor_sync(~0u, psg[e], 2);
        pdg[e] += __shfl_xor_sync(~0u, pdg[e], 1);
        pdg[e] += __shfl_xor_sync(~0u, pdg[e], 2);
    }
    if ((lane & 3) == 0) {
        #pragma unroll
        for (int mt = 0; mt < 4; ++mt) {
            #pragma unroll
            for (int rp = 0; rp < 2; ++rp) {
                int r = mt * 16 + rp * 8 + (lane >> 2);
                sgp[r * 8 + wn]  = psg[mt * 2 + rp];
                sdgp[r * 8 + wn] = pdg[mt * 2 + rp];
            }
        }
    }
    __syncthreads();

    if (tid < 64) {
        float Sg = 0.f, dg = 0.f;
        #pragma unroll
        for (int e = 0; e < 8; ++e) { Sg += sgp[tid * 8 + e]; dg += sdgp[tid * 8 + e]; }

        const float c   = *cin_p;
        const float c2  = *cout_p;
        const float sqc = sqrtf(c);
        const float sq2 = sqrtf(c2);
        const float Sb  = *sSb;
        const float Sv  = svsum[tid];

        const float v0p  = sqrtf(c + Sv);
        const float m    = (sqc * acoshf(fmaxf(v0p / sqc - EPSF, ACOSH_MINF)))
                           / (sqrtf(Sv) + EPSF);
        const float Sw   = m * m * Sg;
        const float dw   = m * dg;
        const float n    = sqrtf(Sw) / sqc + EPSF;
        const float ncl  = fminf(n, CLIPF);
        const float ch   = coshf(ncl);
        const float sfac = sinhf(ncl) / n;
        const float T    = sfac * sfac * Sw;
        const float hp0  = sqrtf(c + T);
        const float dd   = sqc * acoshf(fmaxf(ch, ACOSH_MINF));
        const float d2   = sqc * acoshf(fmaxf(hp0 / sqc - EPSF, ACOSH_MINF));
        const float u0   = sqc - hp0 * hp0 / sqc;
        const float suj2 = (hp0 * hp0 / c) * T;
        const float nrmu = sqrtf(suj2 - u0 * u0);
        const float mlt  = d2 / (nrmu + EPSF);
        const float alph = 1.f - mlt * (hp0 / sqc) * sfac;
        const float m2   = dw / (dd * dd);
        const float beta = alph * m2;
        const float bt0  = -(mlt * u0) * m2;
        const float btsq = bt0 * bt0 + Sb - 2.f * beta * dw + beta * beta * Sw;
        const float nb   = sqrtf(btsq) / sqc + EPSF;
        const float nbcl = fminf(nb, CLIPF);
        const float chb  = coshf(nbcl);
        const float sfb  = sinhf(nbcl) / nb;
        const float gam  = chb * sfac - sfb * beta;
        const float del  = sfb;
        const float Sbi  = gam * gam * Sw + 2.f * gam * del * dw + del * del * Sb;
        const float p0   = sqrtf(c + Sbi);
        const float d3   = sqc * acoshf(fmaxf(p0 / sqc - EPSF, ACOSH_MINF));
        const float qn   = sqrtf(Sbi);
        const float mlt3 = d3 / (qn + EPSF);
        const float nf   = mlt3 * qn / sq2 + EPSF;
        const float nfcl = fminf(nf, CLIPF);
        const float phi  = (sinhf(nfcl) / nf) * mlt3;
        sAw[tid] = phi * gam * m;
        sAb[tid] = phi * del;
        sO0[tid] = sq2 * coshf(nfcl);
    }
    __syncthreads();

    // stores: each warp covers cols wn*32..+31 of all 64 rows
    #pragma unroll
    for (int mt = 0; mt < 4; ++mt) {
        #pragma unroll
        for (int rp = 0; rp < 2; ++rp) {
            int r = mt * 16 + rp * 8 + (lane >> 2);
            float Aw = sAw[r], Ab = sAb[r];
            float* orow = out + (size_t)(row0 + r) * D;
            #pragma unroll
            for (int nt = 0; nt < 4; ++nt) {
                float2 bf = *reinterpret_cast<const float2*>(
                    &sbias[wn * 32 + nt * 8 + 2 * (lane & 3)]);
                float g0 = acc[mt][nt][rp * 2];
                float g1 = acc[mt][nt][rp * 2 + 1];
                float2 o;
                o.x = fmaf(Aw, g0, Ab * bf.x);
                o.y = fmaf(Aw, g1, Ab * bf.y);
                if (wn == 0 && nt == 0 && (lane & 3) == 0) o.x = sO0[r];
                *reinterpret_cast<float2*>(
                    orow + wn * 32 + nt * 8 + 2 * (lane & 3)) = o;
            }
        }
    }
}

extern "C" void kernel_launch(void* const* d_in, const int* in_sizes, int n_in,
                              void* d_out, int out_size)
{
    const float* V    = (const float*)d_in[0];
    const float* cin  = (const float*)d_in[1];
    const float* cout = (const float*)d_in[2];
    const float* W    = (const float*)d_in[3];
    const float* bias = (const float*)d_in[4];
    float* out = (float*)d_out;

    const int nrow = in_sizes[0] / D;             // 131072

    cudaFuncSetAttribute(dh_mma, cudaFuncAttributeMaxDynamicSharedMemorySize,
                         SMEM_DYN);

    prep_w<<<32, 256>>>(W);
    dh_mma<<<nrow / BM, NT, SMEM_DYN>>>(V, cin, cout, bias, out);
}